// round 13
// baseline (speedup 1.0000x reference)
#include <cuda_runtime.h>
#include <math.h>

// Keys cubic kernel, a = -0.5 (matches jax.image.resize method='cubic').
__device__ __forceinline__ float keys_w(float d) {
    d = fabsf(d);
    if (d <= 1.0f) return (1.5f * d - 2.5f) * d * d + 1.0f;
    if (d <  2.0f) return ((-0.5f * d + 2.5f) * d - 4.0f) * d + 2.0f;
    return 0.0f;
}

// jax semantics: x = (i+0.5)*in/out - 0.5; taps floor(x)-1 .. floor(x)+2;
// out-of-range taps dropped and the remaining weights renormalized.
template <int SCALE>
__device__ __forceinline__ int cubic_taps(int i, int in_size, float w[4]) {
    const float inv = 1.0f / (float)SCALE;
    float x = ((float)i + 0.5f) * inv - 0.5f;
    int fl = (int)floorf(x);
    int j0 = fl - 1;
    float s = 0.0f;
#pragma unroll
    for (int k = 0; k < 4; k++) {
        int j = j0 + k;
        float wk = keys_w(x - (float)j);
        if (j < 0 || j >= in_size) wk = 0.0f;
        w[k] = wk;
        s += wk;
    }
    float invs = 1.0f / s;
#pragma unroll
    for (int k = 0; k < 4; k++) w[k] *= invs;
    return j0;
}

// First tap index of the 2x-upsample stencil for output index g (exact, all g).
__device__ __forceinline__ int j2lo(int g) { return (g >> 1) - 2 + (g & 1); }

// ============ fully fused pyramid: cam32 -> ... -> 1024x1024, flipped =======
// Tile = 256 wide x 128 tall, 512 threads, occ 4 (still 64 warps/SM) ->
// only 2048 pyramid preludes (vs 4096), each with halved phase iteration
// counts. Ancestor chain per tile:
//   10x14 cam32 -> 14x22 h64 -> 22x38 h128 -> 36x68 h256 -> 4x upsample.
__global__ void __launch_bounds__(512, 4) fused_kernel(
    const float* __restrict__ cam32,  const float* __restrict__ cam64,
    const float* __restrict__ cam128, const float* __restrict__ cam256,
    const float* __restrict__ w1, const float* __restrict__ b1,
    const float* __restrict__ w2, const float* __restrict__ b2,
    const float* __restrict__ w3, const float* __restrict__ b3,
    float* __restrict__ out)
{
    constexpr int TW = 256, TH = 128, OUT = 1024;
    constexpr int N3C = 68, N3R = 36;   // h256 patch (cols, rows)
    constexpr int N2C = 38, N2R = 22;   // h128
    constexpr int N1C = 22, N1R = 14;   // h64
    constexpr int N0C = 14, N0R = 10;   // cam32
    constexpr int HP  = 256;
    constexpr int NT  = 512;

    __shared__ __align__(16) float  hmem[N3R * HP];   // 36 KB: 4x horizontal buffer
    __shared__ __align__(16) float  raw [N3R * N3C];  // cam256 patch -> h256 patch
    __shared__ __align__(16) float4 wys[TH];          // vertical 4x weights

    // pyramid scratch aliased into hmem (dead until the 4x horizontal pass)
    struct S {
        float  p32 [N0R * N0C];
        float  t1  [N0R * N1C];
        float  h64 [N1R * N1C];
        float  t2  [N1R * N2C];
        float  h128[N2R * N2C];
        float  t3  [N2R * N3C];
        float  c64p [N1R * N1C];
        float  c128p[N2R * N2C];
        float4 w1x[N1C], w1y[N1R];
        float4 w2x[N2C], w2y[N2R];
        float4 w3x[N3C], w3y[N3R];
        int j1x[N1C], j1y[N1R], j2x[N2C], j2y[N2R], j3x[N3C], j3y[N3R];
    };
    static_assert(sizeof(S) <= N3R * HP * 4, "scratch overflows hmem alias");
    S& s = *reinterpret_cast<S*>(hmem);

    const int tx0 = blockIdx.x * TW;
    const int ty0 = blockIdx.y * TH;
    const int b   = blockIdx.z;
    const int t   = threadIdx.x;

    const int ix0 = tx0 / 4 - 2,  iy0 = ty0 / 4 - 2;   // h256 patch origin (even)
    const int hx0 = j2lo(ix0),    hy0 = j2lo(iy0);     // h128 (odd)
    const int qx0 = j2lo(hx0),    qy0 = j2lo(hy0);     // h64 (odd)
    const int px0 = j2lo(qx0),    py0 = j2lo(qy0);     // cam32

    // ---- PREFETCH all cam patches (front-batched LDG burst) ----
    {
        const float* c32b = cam32 + (size_t)b * 32 * 32;
        for (int i = t; i < N0R * N0C; i += NT) {
            int r = i / N0C, c = i % N0C;
            int gr = min(max(py0 + r, 0), 31);
            int gc = min(max(px0 + c, 0), 31);
            s.p32[i] = c32b[gr * 32 + gc];
        }
        const float* c64b = cam64 + (size_t)b * 64 * 64;
        for (int i = t; i < N1R * N1C; i += NT) {
            int r = i / N1C, c = i % N1C;
            int gr = min(max(qy0 + r, 0), 63);
            int gc = min(max(qx0 + c, 0), 63);
            s.c64p[i] = c64b[gr * 64 + gc];
        }
        const float* c128b = cam128 + (size_t)b * 128 * 128;
        for (int i = t; i < N2R * N2C; i += NT) {
            int r = i / N2C, c = i % N2C;
            int gr = min(max(hy0 + r, 0), 127);
            int gc = min(max(hx0 + c, 0), 127);
            s.c128p[i] = c128b[gr * 128 + gc];
        }
        const float* c256b = cam256 + (size_t)b * 256 * 256;
        for (int i = t; i < N3R * N3C; i += NT) {
            int r = i / N3C, c = i % N3C;
            int gr = min(max(iy0 + r, 0), 255);
            int gc = min(max(ix0 + c, 0), 255);
            raw[i] = c256b[gr * 256 + gc];       // consumed in-place by stage 3
        }
    }

    // ---- vertical 4x weight table (overlaps in-flight prefetch LDGs) ----
    if (t < TH) {
        float w[4];
        cubic_taps<4>(ty0 + t, 256, w);
        wys[t] = make_float4(w[0], w[1], w[2], w[3]);
    }
    // ---- stage-1..3 weight tables (200 entries, one per thread) ----
    {
        constexpr int O1 = N1C, O2 = O1 + N1R, O3 = O2 + N2C, O4 = O3 + N2R;
        constexpr int O5 = O4 + N3C, O6 = O5 + N3R;
        const int e = t - TH;
        if (e >= 0 && e < O6) {
            float w[4];
            if (e < O1) {
                int i = e;
                int j0 = cubic_taps<2>(min(max(qx0 + i, 0), 63), 32, w);
                s.w1x[i] = make_float4(w[0], w[1], w[2], w[3]);
                s.j1x[i] = j0 - px0;
            } else if (e < O2) {
                int i = e - O1;
                int j0 = cubic_taps<2>(min(max(qy0 + i, 0), 63), 32, w);
                s.w1y[i] = make_float4(w[0], w[1], w[2], w[3]);
                s.j1y[i] = j0 - py0;
            } else if (e < O3) {
                int i = e - O2;
                int j0 = cubic_taps<2>(min(max(hx0 + i, 0), 127), 64, w);
                s.w2x[i] = make_float4(w[0], w[1], w[2], w[3]);
                s.j2x[i] = j0 - qx0;
            } else if (e < O4) {
                int i = e - O3;
                int j0 = cubic_taps<2>(min(max(hy0 + i, 0), 127), 64, w);
                s.w2y[i] = make_float4(w[0], w[1], w[2], w[3]);
                s.j2y[i] = j0 - qy0;
            } else if (e < O5) {
                int i = e - O4;
                int j0 = cubic_taps<2>(min(max(ix0 + i, 0), 255), 128, w);
                s.w3x[i] = make_float4(w[0], w[1], w[2], w[3]);
                s.j3x[i] = j0 - hx0;
            } else {
                int i = e - O5;
                int j0 = cubic_taps<2>(min(max(iy0 + i, 0), 255), 128, w);
                s.w3y[i] = make_float4(w[0], w[1], w[2], w[3]);
                s.j3y[i] = j0 - hy0;
            }
        }
    }
    __syncthreads();

    // ---- stage 1 horizontal: N0R rows x N1C cols ----
    for (int i = t; i < N0R * N1C; i += NT) {
        int r = i / N1C, c = i % N1C;
        const float4 w = s.w1x[c];
        const float* rp = &s.p32[r * N0C + s.j1x[c]];
        s.t1[i] = w.x*rp[0] + w.y*rp[1] + w.z*rp[2] + w.w*rp[3];
    }
    __syncthreads();

    // ---- stage 1 vertical + conv/ReLU -> h64 ----
    {
        const float fa = w1[0], fcb = w1[1], fc = b1[0];
        for (int i = t; i < N1R * N1C; i += NT) {
            int r = i / N1C, c = i % N1C;
            const float4 w = s.w1y[r];
            const float* cp = &s.t1[s.j1y[r] * N1C + c];
            float up = w.x*cp[0] + w.y*cp[N1C] + w.z*cp[2*N1C] + w.w*cp[3*N1C];
            s.h64[i] = fmaxf(fa * up + fcb * s.c64p[i] + fc, 0.0f);
        }
    }
    __syncthreads();

    // ---- stage 2 horizontal: N1R rows x N2C cols ----
    for (int i = t; i < N1R * N2C; i += NT) {
        int r = i / N2C, c = i % N2C;
        const float4 w = s.w2x[c];
        const float* rp = &s.h64[r * N1C + s.j2x[c]];
        s.t2[i] = w.x*rp[0] + w.y*rp[1] + w.z*rp[2] + w.w*rp[3];
    }
    __syncthreads();

    // ---- stage 2 vertical + conv/ReLU -> h128 ----
    {
        const float fa = w2[0], fcb = w2[1], fc = b2[0];
        for (int i = t; i < N2R * N2C; i += NT) {
            int r = i / N2C, c = i % N2C;
            const float4 w = s.w2y[r];
            const float* cp = &s.t2[s.j2y[r] * N2C + c];
            float up = w.x*cp[0] + w.y*cp[N2C] + w.z*cp[2*N2C] + w.w*cp[3*N2C];
            s.h128[i] = fmaxf(fa * up + fcb * s.c128p[i] + fc, 0.0f);
        }
    }
    __syncthreads();

    // ---- stage 3 horizontal: N2R rows x N3C cols ----
    for (int i = t; i < N2R * N3C; i += NT) {
        int r = i / N3C, c = i % N3C;
        const float4 w = s.w3x[c];
        const float* rp = &s.h128[r * N2C + s.j3x[c]];
        s.t3[i] = w.x*rp[0] + w.y*rp[1] + w.z*rp[2] + w.w*rp[3];
    }
    __syncthreads();

    // ---- stage 3 vertical + conv/ReLU (cam256 already in raw, in-place) ----
    {
        const float fa = w3[0], fcb = w3[1], fc = b3[0];
        for (int i = t; i < N3R * N3C; i += NT) {
            int r = i / N3C, c = i % N3C;
            const float4 w = s.w3y[r];
            const float* cp = &s.t3[s.j3y[r] * N3C + c];
            float up = w.x*cp[0] + w.y*cp[N3C] + w.z*cp[2*N3C] + w.w*cp[3*N3C];
            raw[i] = fmaxf(fa * up + fcb * raw[i] + fc, 0.0f);
        }
    }
    __syncthreads();   // raw = h256 patch; scratch S (hmem) now dead

    // ---- 4x horizontal: 4 consecutive out-cols from 5 inputs ----
    // Per-thread weights recomputed here (wxs table doesn't fit in smem).
    {
        const int cg = t & 63;        // 64 column groups cover 256 cols
        const int r0 = t >> 6;        // 8 row slots
        float wA[4], wB[4], wC[4], wD[4];
        cubic_taps<4>(tx0 + 4*cg + 0, 256, wA);
        cubic_taps<4>(tx0 + 4*cg + 1, 256, wB);
        cubic_taps<4>(tx0 + 4*cg + 2, 256, wC);
        cubic_taps<4>(tx0 + 4*cg + 3, 256, wD);
        for (int r = r0; r < N3R; r += 8) {
            const float* rp = &raw[r * N3C + cg];
            float a0 = rp[0], a1 = rp[1], a2 = rp[2], a3 = rp[3], a4 = rp[4];
            float4 v;
            v.x = wA[0]*a0 + wA[1]*a1 + wA[2]*a2 + wA[3]*a3;   // phase 0
            v.y = wB[0]*a0 + wB[1]*a1 + wB[2]*a2 + wB[3]*a3;   // phase 1
            v.z = wC[0]*a1 + wC[1]*a2 + wC[2]*a3 + wC[3]*a4;   // phase 2
            v.w = wD[0]*a1 + wD[1]*a2 + wD[2]*a3 + wD[3]*a4;   // phase 3
            *(float4*)&hmem[r * HP + 4*cg] = v;
        }
    }
    __syncthreads();

    // ---- 4x vertical: rolling 5-register window over 4 consecutive groups
    // thread (c4, sv): output rows 16sv..16sv+15, cols tx0+4*c4..+3.
    {
        const int c4 = t & 63;
        const int sv = t >> 6;        // 8 segments of 16 rows
        const int cc = 4 * c4;
        float* outb = out + (size_t)(gridDim.z - 1 - b) * OUT * OUT;
        const float* hb = &hmem[cc];
        float* op = &outb[(size_t)(ty0 + 16*sv) * OUT + tx0 + cc];
        const float4* wy = &wys[16*sv];

        float4 r0 = *(const float4*)&hb[(4*sv+0) * HP];
        float4 r1 = *(const float4*)&hb[(4*sv+1) * HP];
        float4 r2 = *(const float4*)&hb[(4*sv+2) * HP];
        float4 r3 = *(const float4*)&hb[(4*sv+3) * HP];
        float4 r4 = *(const float4*)&hb[(4*sv+4) * HP];

#define EMIT(WI, A, B, C, D, RO)                                          \
        {                                                                 \
            const float4 w = wy[WI];                                      \
            float4 v;                                                     \
            v.x = w.x*A.x + w.y*B.x + w.z*C.x + w.w*D.x;                  \
            v.y = w.x*A.y + w.y*B.y + w.z*C.y + w.w*D.y;                  \
            v.z = w.x*A.z + w.y*B.z + w.z*C.z + w.w*D.z;                  \
            v.w = w.x*A.w + w.y*B.w + w.z*C.w + w.w*D.w;                  \
            __stcs((float4*)(op + (size_t)(RO) * OUT), v);                \
        }
        EMIT(0,  r0, r1, r2, r3, 0)
        EMIT(1,  r0, r1, r2, r3, 1)
        EMIT(2,  r1, r2, r3, r4, 2)
        EMIT(3,  r1, r2, r3, r4, 3)
        r0 = *(const float4*)&hb[(4*sv+5) * HP];
        EMIT(4,  r1, r2, r3, r4, 4)
        EMIT(5,  r1, r2, r3, r4, 5)
        EMIT(6,  r2, r3, r4, r0, 6)
        EMIT(7,  r2, r3, r4, r0, 7)
        r1 = *(const float4*)&hb[(4*sv+6) * HP];
        EMIT(8,  r2, r3, r4, r0, 8)
        EMIT(9,  r2, r3, r4, r0, 9)
        EMIT(10, r3, r4, r0, r1, 10)
        EMIT(11, r3, r4, r0, r1, 11)
        r2 = *(const float4*)&hb[(4*sv+7) * HP];
        EMIT(12, r3, r4, r0, r1, 12)
        EMIT(13, r3, r4, r0, r1, 13)
        EMIT(14, r4, r0, r1, r2, 14)
        EMIT(15, r4, r0, r1, r2, 15)
#undef EMIT
    }
}

extern "C" void kernel_launch(void* const* d_in, const int* in_sizes, int n_in,
                              void* d_out, int out_size)
{
    (void)in_sizes; (void)n_in; (void)out_size;
    const float* cam256 = (const float*)d_in[0];
    const float* cam128 = (const float*)d_in[1];
    const float* cam64  = (const float*)d_in[2];
    const float* cam32  = (const float*)d_in[3];
    const float* w1 = (const float*)d_in[4];
    const float* b1 = (const float*)d_in[5];
    const float* w2 = (const float*)d_in[6];
    const float* b2 = (const float*)d_in[7];
    const float* w3 = (const float*)d_in[8];
    const float* b3 = (const float*)d_in[9];
    float* out = (float*)d_out;

    fused_kernel<<<dim3(4, 8, 64), 512>>>(
        cam32, cam64, cam128, cam256, w1, b1, w2, b2, w3, b3, out);
}

// round 14
// speedup vs baseline: 1.9214x; 1.9214x over previous
#include <cuda_runtime.h>
#include <math.h>

// Keys cubic kernel, a = -0.5 (matches jax.image.resize method='cubic').
__device__ __forceinline__ float keys_w(float d) {
    d = fabsf(d);
    if (d <= 1.0f) return (1.5f * d - 2.5f) * d * d + 1.0f;
    if (d <  2.0f) return ((-0.5f * d + 2.5f) * d - 4.0f) * d + 2.0f;
    return 0.0f;
}

// jax semantics: x = (i+0.5)*in/out - 0.5; taps floor(x)-1 .. floor(x)+2;
// out-of-range taps dropped and the remaining weights renormalized.
template <int SCALE>
__device__ __forceinline__ int cubic_taps(int i, int in_size, float w[4]) {
    const float inv = 1.0f / (float)SCALE;
    float x = ((float)i + 0.5f) * inv - 0.5f;
    int fl = (int)floorf(x);
    int j0 = fl - 1;
    float s = 0.0f;
#pragma unroll
    for (int k = 0; k < 4; k++) {
        int j = j0 + k;
        float wk = keys_w(x - (float)j);
        if (j < 0 || j >= in_size) wk = 0.0f;
        w[k] = wk;
        s += wk;
    }
    float invs = 1.0f / s;
#pragma unroll
    for (int k = 0; k < 4; k++) w[k] *= invs;
    return j0;
}

// First tap index of the 2x-upsample stencil for output index g (exact, all g).
__device__ __forceinline__ int j2lo(int g) { return (g >> 1) - 2 + (g & 1); }

// ============ fully fused pyramid: cam32 -> ... -> 1024x1024, flipped =======
// Per 128x128 output tile, compute the whole ancestor chain in smem:
//   10x10 cam32 patch -> 14x14 h64 -> 22x22 h128 -> 36x36 h256 -> 4x upsample.
// OOB patch slots hold clamped (finite) values and always get weight 0 from
// the renormalized cubic weights, so the cascade is exact.
__global__ void __launch_bounds__(256, 8) fused_kernel(
    const float* __restrict__ cam32,  const float* __restrict__ cam64,
    const float* __restrict__ cam128, const float* __restrict__ cam256,
    const float* __restrict__ w1, const float* __restrict__ b1,
    const float* __restrict__ w2, const float* __restrict__ b2,
    const float* __restrict__ w3, const float* __restrict__ b3,
    float* __restrict__ out)
{
    constexpr int TILE = 128, OUT = 1024;
    constexpr int N3 = 36, N2 = 22, N1 = 14, N0 = 10;
    constexpr int HP = 128;

    __shared__ __align__(16) float  raw [N3 * N3];   // h256 patch
    __shared__ __align__(16) float  hmem[N3 * HP];   // 4x horizontal buffer
    __shared__ __align__(16) float4 wxs[TILE];
    __shared__ __align__(16) float4 wys[TILE];

    // pyramid scratch aliased into hmem (dead until the 4x horizontal pass)
    struct S {
        float  p32 [N0 * N0];
        float  t1  [N0 * N1];
        float  h64 [N1 * N1];
        float  t2  [N1 * N2];
        float  h128[N2 * N2];
        float  t3  [N2 * N3];
        float4 w1x[N1], w1y[N1];
        float4 w2x[N2], w2y[N2];
        float4 w3x[N3], w3y[N3];
        int j1x[N1], j1y[N1], j2x[N2], j2y[N2], j3x[N3], j3y[N3];
    };
    static_assert(sizeof(S) <= N3 * HP * 4, "scratch overflows hmem alias");
    S& s = *reinterpret_cast<S*>(hmem);

    const int tx0 = blockIdx.x * TILE;
    const int ty0 = blockIdx.y * TILE;
    const int b   = blockIdx.z;
    const int t   = threadIdx.x;

    const int ix0 = tx0 / 4 - 2,  iy0 = ty0 / 4 - 2;   // h256 patch origin
    const int hx0 = j2lo(ix0),    hy0 = j2lo(iy0);     // h128
    const int qx0 = j2lo(hx0),    qy0 = j2lo(hy0);     // h64
    const int px0 = j2lo(qx0),    py0 = j2lo(qy0);     // cam32

    // ---- stage-4 weight tables ----
    {
        float w[4];
        if (t < TILE) {
            cubic_taps<4>(tx0 + t, 256, w);
            wxs[t] = make_float4(w[0], w[1], w[2], w[3]);
        } else {
            cubic_taps<4>(ty0 + (t - TILE), 256, w);
            wys[t - TILE] = make_float4(w[0], w[1], w[2], w[3]);
        }
    }
    // ---- stage-1..3 weight tables (144 entries, one per thread) ----
    if (t < 2 * (N1 + N2 + N3)) {
        int e = t;
        float w[4];
        if (e < 2 * N1) {
            bool ya = e >= N1; int i = ya ? e - N1 : e;
            int g = min(max((ya ? qy0 : qx0) + i, 0), 63);
            int j0 = cubic_taps<2>(g, 32, w);
            float4 wv = make_float4(w[0], w[1], w[2], w[3]);
            if (ya) { s.w1y[i] = wv; s.j1y[i] = j0 - py0; }
            else    { s.w1x[i] = wv; s.j1x[i] = j0 - px0; }
        } else if (e < 2 * N1 + 2 * N2) {
            e -= 2 * N1;
            bool ya = e >= N2; int i = ya ? e - N2 : e;
            int g = min(max((ya ? hy0 : hx0) + i, 0), 127);
            int j0 = cubic_taps<2>(g, 64, w);
            float4 wv = make_float4(w[0], w[1], w[2], w[3]);
            if (ya) { s.w2y[i] = wv; s.j2y[i] = j0 - qy0; }
            else    { s.w2x[i] = wv; s.j2x[i] = j0 - qx0; }
        } else {
            e -= 2 * N1 + 2 * N2;
            bool ya = e >= N3; int i = ya ? e - N3 : e;
            int g = min(max((ya ? iy0 : ix0) + i, 0), 255);
            int j0 = cubic_taps<2>(g, 128, w);
            float4 wv = make_float4(w[0], w[1], w[2], w[3]);
            if (ya) { s.w3y[i] = wv; s.j3y[i] = j0 - hy0; }
            else    { s.w3x[i] = wv; s.j3x[i] = j0 - hx0; }
        }
    }

    // ---- cam32 patch (clamped) ----
    {
        const float* c32b = cam32 + (size_t)b * 32 * 32;
        for (int i = t; i < N0 * N0; i += 256) {
            int r = i / N0, c = i % N0;
            int gr = min(max(py0 + r, 0), 31);
            int gc = min(max(px0 + c, 0), 31);
            s.p32[i] = c32b[gr * 32 + gc];
        }
    }
    __syncthreads();

    // ---- stage 1 horizontal: N0 rows x N1 cols ----
    for (int i = t; i < N0 * N1; i += 256) {
        int r = i / N1, c = i % N1;
        const float4 w = s.w1x[c];
        const float* rp = &s.p32[r * N0 + s.j1x[c]];
        s.t1[i] = w.x*rp[0] + w.y*rp[1] + w.z*rp[2] + w.w*rp[3];
    }
    __syncthreads();

    // ---- stage 1 vertical + conv/ReLU with cam64 -> h64 ----
    {
        const float fa = w1[0], fcb = w1[1], fc = b1[0];
        const float* c64b = cam64 + (size_t)b * 64 * 64;
        for (int i = t; i < N1 * N1; i += 256) {
            int r = i / N1, c = i % N1;
            const float4 w = s.w1y[r];
            const float* cp = &s.t1[s.j1y[r] * N1 + c];
            float up = w.x*cp[0] + w.y*cp[N1] + w.z*cp[2*N1] + w.w*cp[3*N1];
            int gy = min(max(qy0 + r, 0), 63);
            int gx = min(max(qx0 + c, 0), 63);
            s.h64[i] = fmaxf(fa * up + fcb * c64b[gy * 64 + gx] + fc, 0.0f);
        }
    }
    __syncthreads();

    // ---- stage 2 horizontal: N1 rows x N2 cols ----
    for (int i = t; i < N1 * N2; i += 256) {
        int r = i / N2, c = i % N2;
        const float4 w = s.w2x[c];
        const float* rp = &s.h64[r * N1 + s.j2x[c]];
        s.t2[i] = w.x*rp[0] + w.y*rp[1] + w.z*rp[2] + w.w*rp[3];
    }
    __syncthreads();

    // ---- stage 2 vertical + conv/ReLU with cam128 -> h128 ----
    {
        const float fa = w2[0], fcb = w2[1], fc = b2[0];
        const float* c128b = cam128 + (size_t)b * 128 * 128;
        for (int i = t; i < N2 * N2; i += 256) {
            int r = i / N2, c = i % N2;
            const float4 w = s.w2y[r];
            const float* cp = &s.t2[s.j2y[r] * N2 + c];
            float up = w.x*cp[0] + w.y*cp[N2] + w.z*cp[2*N2] + w.w*cp[3*N2];
            int gy = min(max(hy0 + r, 0), 127);
            int gx = min(max(hx0 + c, 0), 127);
            s.h128[i] = fmaxf(fa * up + fcb * c128b[gy * 128 + gx] + fc, 0.0f);
        }
    }
    __syncthreads();

    // ---- stage 3 horizontal: N2 rows x N3 cols ----
    for (int i = t; i < N2 * N3; i += 256) {
        int r = i / N3, c = i % N3;
        const float4 w = s.w3x[c];
        const float* rp = &s.h128[r * N2 + s.j3x[c]];
        s.t3[i] = w.x*rp[0] + w.y*rp[1] + w.z*rp[2] + w.w*rp[3];
    }
    __syncthreads();

    // ---- stage 3 vertical + conv/ReLU with cam256 -> raw (h256 patch) ----
    {
        const float fa = w3[0], fcb = w3[1], fc = b3[0];
        const float* c256b = cam256 + (size_t)b * 256 * 256;
        for (int i = t; i < N3 * N3; i += 256) {
            int r = i / N3, c = i % N3;
            const float4 w = s.w3y[r];
            const float* cp = &s.t3[s.j3y[r] * N3 + c];
            float up = w.x*cp[0] + w.y*cp[N3] + w.z*cp[2*N3] + w.w*cp[3*N3];
            int gy = min(max(iy0 + r, 0), 255);
            int gx = min(max(ix0 + c, 0), 255);
            raw[i] = fmaxf(fa * up + fcb * c256b[gy * 256 + gx] + fc, 0.0f);
        }
    }
    __syncthreads();   // raw ready; scratch S (hmem) now dead

    // ---- 4x horizontal: 4 consecutive out-cols from 5 inputs ----
    {
        const int cg = t & 31;
        const int r0 = t >> 5;
        const float4 wA = wxs[4*cg+0];
        const float4 wB = wxs[4*cg+1];
        const float4 wC = wxs[4*cg+2];
        const float4 wD = wxs[4*cg+3];
        for (int r = r0; r < N3; r += 8) {
            const float* rp = &raw[r * N3 + cg];
            float a0 = rp[0], a1 = rp[1], a2 = rp[2], a3 = rp[3], a4 = rp[4];
            float4 v;
            v.x = wA.x*a0 + wA.y*a1 + wA.z*a2 + wA.w*a3;   // phase 0
            v.y = wB.x*a0 + wB.y*a1 + wB.z*a2 + wB.w*a3;   // phase 1
            v.z = wC.x*a1 + wC.y*a2 + wC.z*a3 + wC.w*a4;   // phase 2
            v.w = wD.x*a1 + wD.y*a2 + wD.z*a3 + wD.w*a4;   // phase 3
            *(float4*)&hmem[r * HP + 4*cg] = v;
        }
    }
    __syncthreads();

    // ---- 4x vertical: rolling 5-register window over 4 consecutive groups
    {
        const int c4 = t & 31;
        const int sv = t >> 5;
        const int cc = 4 * c4;
        float* outb = out + (size_t)(gridDim.z - 1 - b) * OUT * OUT;
        const float* hb = &hmem[cc];
        float* op = &outb[(size_t)(ty0 + 16*sv) * OUT + tx0 + cc];
        const float4* wy = &wys[16*sv];

        float4 r0 = *(const float4*)&hb[(4*sv+0) * HP];
        float4 r1 = *(const float4*)&hb[(4*sv+1) * HP];
        float4 r2 = *(const float4*)&hb[(4*sv+2) * HP];
        float4 r3 = *(const float4*)&hb[(4*sv+3) * HP];
        float4 r4 = *(const float4*)&hb[(4*sv+4) * HP];

#define EMIT(WI, A, B, C, D, RO)                                          \
        {                                                                 \
            const float4 w = wy[WI];                                      \
            float4 v;                                                     \
            v.x = w.x*A.x + w.y*B.x + w.z*C.x + w.w*D.x;                  \
            v.y = w.x*A.y + w.y*B.y + w.z*C.y + w.w*D.y;                  \
            v.z = w.x*A.z + w.y*B.z + w.z*C.z + w.w*D.z;                  \
            v.w = w.x*A.w + w.y*B.w + w.z*C.w + w.w*D.w;                  \
            __stcs((float4*)(op + (size_t)(RO) * OUT), v);                \
        }
        EMIT(0,  r0, r1, r2, r3, 0)
        EMIT(1,  r0, r1, r2, r3, 1)
        EMIT(2,  r1, r2, r3, r4, 2)
        EMIT(3,  r1, r2, r3, r4, 3)
        r0 = *(const float4*)&hb[(4*sv+5) * HP];
        EMIT(4,  r1, r2, r3, r4, 4)
        EMIT(5,  r1, r2, r3, r4, 5)
        EMIT(6,  r2, r3, r4, r0, 6)
        EMIT(7,  r2, r3, r4, r0, 7)
        r1 = *(const float4*)&hb[(4*sv+6) * HP];
        EMIT(8,  r2, r3, r4, r0, 8)
        EMIT(9,  r2, r3, r4, r0, 9)
        EMIT(10, r3, r4, r0, r1, 10)
        EMIT(11, r3, r4, r0, r1, 11)
        r2 = *(const float4*)&hb[(4*sv+7) * HP];
        EMIT(12, r3, r4, r0, r1, 12)
        EMIT(13, r3, r4, r0, r1, 13)
        EMIT(14, r4, r0, r1, r2, 14)
        EMIT(15, r4, r0, r1, r2, 15)
#undef EMIT
    }
}

extern "C" void kernel_launch(void* const* d_in, const int* in_sizes, int n_in,
                              void* d_out, int out_size)
{
    (void)in_sizes; (void)n_in; (void)out_size;
    const float* cam256 = (const float*)d_in[0];
    const float* cam128 = (const float*)d_in[1];
    const float* cam64  = (const float*)d_in[2];
    const float* cam32  = (const float*)d_in[3];
    const float* w1 = (const float*)d_in[4];
    const float* b1 = (const float*)d_in[5];
    const float* w2 = (const float*)d_in[6];
    const float* b2 = (const float*)d_in[7];
    const float* w3 = (const float*)d_in[8];
    const float* b3 = (const float*)d_in[9];
    float* out = (float*)d_out;

    fused_kernel<<<dim3(8, 8, 64), 256>>>(
        cam32, cam64, cam128, cam256, w1, b1, w2, b2, w3, b3, out);
}